// round 14
// baseline (speedup 1.0000x reference)
#include <cuda_runtime.h>
#include <cstdint>

#define NCTA 128
#define NTHR 768
#define NGRP 3
#define TQ   200
#define INF  171
#define OUTF 171
#define HIDQ 1024
#define KSX  32
#define KSH  128
#define KS1  (KSX + KSH)   // 160 = 10 chunks
#define KS2  (2 * KSH)     // 256 = 16 chunks
#define KSD  128
#define DCTA 22
#define HFR  (KSH * 1024)
#define XFR  (KSX * 1024)
#define CHKS 16
#define CHB  (CHKS * 1024)
#define NBUF 3
#define HDR  128                                  // 9 mbarriers
#define REDOFF (HDR + NGRP * NBUF * CHB)          // after 9 ring slots
#define SMEMSZ (REDOFF + 2 * 256 * 17 * 4)        // + two 17-padded acc zones

__device__ __align__(16) float2 g_W1[NCTA * KS1 * 128];
__device__ __align__(16) float2 g_W2[NCTA * KS2 * 128];
__device__ __align__(16) float2 g_W3[NCTA * KS2 * 128];
__device__ __align__(16) float2 g_Wd[DCTA * KSD * 32];
__device__ float g_bias1[4 * HIDQ];
__device__ float g_bias2[4 * HIDQ];
__device__ float g_bias3[4 * HIDQ];
__device__ float g_biasd[176];
__device__ __align__(16) float g_xfrag[TQ * XFR];
__device__ __align__(16) float g_h1[2 * HFR];
__device__ __align__(16) float g_h2[2 * HFR];
__device__ __align__(16) float g_h3[2 * HFR];
__device__ __align__(16) float g_of[2 * XFR];
__device__ unsigned g_cnt;
__device__ volatile unsigned g_gen;

__constant__ int c_cb1[4] = {0, 4, 7, 10};   // layer1 chunk bases per group
__constant__ int c_cb2[4] = {0, 6, 11, 16};  // layer2/3 chunk bases per group

__device__ __forceinline__ float tf32r(float x) {
    uint32_t y;
    asm("cvt.rna.tf32.f32 %0, %1;" : "=r"(y) : "f"(x));
    return __uint_as_float(y);
}
__device__ __forceinline__ void mma8(float* c, uint32_t a0, uint32_t a1, uint32_t a2,
                                     uint32_t a3, uint32_t b0, uint32_t b1) {
    asm("mma.sync.aligned.m16n8k8.row.col.f32.tf32.tf32.f32 "
        "{%0,%1,%2,%3},{%4,%5,%6,%7},{%8,%9},{%0,%1,%2,%3};"
        : "+f"(c[0]), "+f"(c[1]), "+f"(c[2]), "+f"(c[3])
        : "r"(a0), "r"(a1), "r"(a2), "r"(a3), "r"(b0), "r"(b1));
}
__device__ __forceinline__ float sigm(float x) { return 1.f / (1.f + __expf(-x)); }
__device__ __forceinline__ uint32_t smem_u32(const void* p) {
    return (uint32_t)__cvta_generic_to_shared(p);
}
__device__ __forceinline__ void mbar_init(uint32_t a, uint32_t cnt) {
    asm volatile("mbarrier.init.shared.b64 [%0], %1;" :: "r"(a), "r"(cnt) : "memory");
}
__device__ __forceinline__ void mbar_expect_tx(uint32_t a, uint32_t bytes) {
    asm volatile("mbarrier.arrive.expect_tx.shared.b64 _, [%0], %1;"
                 :: "r"(a), "r"(bytes) : "memory");
}
__device__ __forceinline__ void bulk_g2s(uint32_t dst, const void* src, uint32_t bytes,
                                         uint32_t mbar) {
    asm volatile("cp.async.bulk.shared::cta.global.mbarrier::complete_tx::bytes "
                 "[%0], [%1], %2, [%3];"
                 :: "r"(dst), "l"(src), "r"(bytes), "r"(mbar) : "memory");
}
__device__ __forceinline__ void mbar_wait(uint32_t a, int parity) {
    asm volatile(
        "{\n\t.reg .pred P;\n\t"
        "WL%=:\n\t"
        "mbarrier.try_wait.parity.acquire.cta.shared::cta.b64 P, [%0], %1, 0x989680;\n\t"
        "@!P bra WL%=;\n\t}"
        :: "r"(a), "r"(parity) : "memory");
}
__device__ __forceinline__ float4 lds128(uint32_t a) {
    float4 v;
    asm volatile("ld.shared.v4.f32 {%0,%1,%2,%3}, [%4];"
                 : "=f"(v.x), "=f"(v.y), "=f"(v.z), "=f"(v.w) : "r"(a));
    return v;
}
__device__ __forceinline__ void barg(int g) {   // per-group named barrier (256 thr)
    asm volatile("bar.sync %0, %1;" :: "r"(g + 1), "r"(256) : "memory");
}

// monotonic grid barrier; all 128 CTAs resident (1/SM)
__device__ __forceinline__ void gridbar() {
    __syncthreads();
    if (threadIdx.x == 0) {
        __threadfence();
        unsigned arr = atomicAdd(&g_cnt, 1u);
        unsigned mygen = arr / NCTA + 1u;
        if (arr % NCTA == NCTA - 1u) {
            __threadfence();
            g_gen = mygen;
        } else {
            while ((int)(g_gen - mygen) < 0) { __nanosleep(32); }
        }
        __threadfence();
    }
    __syncthreads();
}

__device__ __forceinline__ void initacc(float acc[16], const float* bias, int ct, int lane) {
#pragma unroll
    for (int nt = 0; nt < 4; ++nt) {
        int col = nt * HIDQ + (ct << 3) + ((lane & 3) << 1);
        float b0 = bias[col], b1 = bias[col + 1];
        acc[4 * nt] = b0; acc[4 * nt + 1] = b1;
        acc[4 * nt + 2] = b0; acc[4 * nt + 3] = b1;
    }
}

// group-local GEMM span over ks [ksbase, ksbase+nksg): A via depth-8 __ldcg ring,
// W via this group's 3-deep TMA ring. nksg multiple of 16.
__device__ __forceinline__ void layer_mm(float acc[16], const float* A0, const float* A1,
                                         int nks0, int ksbase, int nksg, const char* wsrc,
                                         const uint32_t* wsm, const uint32_t* mb, int* ph,
                                         int g, int tid, int mt, int lane) {
    const float4* A04 = (const float4*)A0;
    const float4* A14 = (const float4*)A1;
    float4 ab[8];
#pragma unroll
    for (int i = 0; i < 8; ++i) {
        int ks = ksbase + i;
        const float4* src = (ks < nks0) ? (A04 + (ks * 8 + mt) * 32)
                                        : (A14 + ((ks - nks0) * 8 + mt) * 32);
        ab[i] = __ldcg(src + lane);
    }
    int nch = nksg >> 4;
    const char* wg = wsrc + (size_t)(ksbase >> 4) * CHB;
    if ((tid & 255) == 0) {
#pragma unroll
        for (int k = 0; k < 2; ++k) {
            mbar_expect_tx(mb[k], CHB);
            bulk_g2s(wsm[k], wg + (size_t)k * CHB, CHB, mb[k]);
        }
    }
    for (int c = 0; c < nch; ++c) {
        int b = c % NBUF;
        mbar_wait(mb[b], ph[b]);
        ph[b] ^= 1;
        uint32_t wb = wsm[b] + (lane << 4);
#pragma unroll
        for (int j = 0; j < 16; ++j) {
            int ksl = (c << 4) + j;
            int s = ksl & 7;
            float4 a = ab[s];
            int pf = ksl + 8;
            if (pf < nksg) {
                int ks = ksbase + pf;
                const float4* src = (ks < nks0) ? (A04 + (ks * 8 + mt) * 32)
                                                : (A14 + ((ks - nks0) * 8 + mt) * 32);
                ab[s] = __ldcg(src + lane);
            }
            float4 w0 = lds128(wb + j * 1024);
            float4 w1 = lds128(wb + j * 1024 + 512);
            uint32_t a0 = __float_as_uint(a.x), a1 = __float_as_uint(a.y);
            uint32_t a2 = __float_as_uint(a.z), a3 = __float_as_uint(a.w);
            mma8(acc + 0,  a0, a1, a2, a3, __float_as_uint(w0.x), __float_as_uint(w0.y));
            mma8(acc + 4,  a0, a1, a2, a3, __float_as_uint(w0.z), __float_as_uint(w0.w));
            mma8(acc + 8,  a0, a1, a2, a3, __float_as_uint(w1.x), __float_as_uint(w1.y));
            mma8(acc + 12, a0, a1, a2, a3, __float_as_uint(w1.z), __float_as_uint(w1.w));
        }
        barg(g);
        if ((tid & 255) == 0 && c + 2 < nch) {
            int b2 = (c + 2) % NBUF;
            mbar_expect_tx(mb[b2], CHB);
            bulk_g2s(wsm[b2], wg + (size_t)(c + 2) * CHB, CHB, mb[b2]);
        }
    }
}

__device__ __forceinline__ void lstm_epi(const float acc[16], float cst[4], float* hdst,
                                         int ct, int mt, int lane) {
#pragma unroll
    for (int j = 0; j < 4; ++j) {
        float ig = sigm(acc[0 + j]);
        float fg = sigm(acc[4 + j]);
        float gg = tanhf(acc[8 + j]);
        float og = sigm(acc[12 + j]);
        float cc = fg * cst[j] + ig * gg;
        cst[j] = cc;
        float h = og * tanhf(cc);
        int r = (lane >> 2) + ((j & 2) << 2);
        int c = ((lane & 3) << 1) + (j & 1);
        int aq = ((c >= 4) ? 2 : 0) + ((r >= 8) ? 1 : 0);
        int lp = ((r & 7) << 2) + (c & 3);
        hdst[((((ct << 3) + mt) << 5) + lp) * 4 + aq] = tf32r(h);
    }
}

__device__ __forceinline__ float wfetch(const float* Wih, const float* Whh, int gr, int k,
                                        int kxt, int kxv) {
    if (k < kxt) return (k < kxv) ? Wih[gr * kxv + k] : 0.f;
    return Whh[gr * HIDQ + (k - kxt)];
}
__device__ __forceinline__ void fmt_slice(float2* dst, const float* Wih, const float* Whh,
                                          int KS, int kxt, int kxv, int ct, int tid) {
    for (int i = tid; i < KS * 128; i += NTHR) {
        int nt = i & 3;
        int lane = (i >> 2) & 31;
        int ks = i >> 7;
        int gr = nt * HIDQ + (ct << 3) + (lane >> 2);
        int k0 = (ks << 3) + (lane & 3);
        float v0 = wfetch(Wih, Whh, gr, k0, kxt, kxv);
        float v1 = wfetch(Wih, Whh, gr, k0 + 4, kxt, kxv);
        size_t off = ((size_t)ct * KS + ks) * 128 + (nt >> 1) * 64 + lane * 2 + (nt & 1);
        dst[off] = make_float2(tf32r(v0), tf32r(v1));
    }
}
__device__ __forceinline__ float ldx(const float* s, int b, int t, int f) {
    return (f < INF) ? tf32r(s[(b * TQ + t) * INF + f]) : 0.f;
}

// ---------------- single fused kernel: setup + persistent LSTM ----------------
__global__ void __launch_bounds__(NTHR, 1)
lstm_main(const float* __restrict__ seq, const int* __restrict__ pcn,
          const int* __restrict__ pgn,
          const float* W_ih1, const float* W_hh1, const float* b_ih1, const float* b_hh1,
          const float* W_ih2, const float* W_hh2, const float* b_ih2, const float* b_hh2,
          const float* W_ih3, const float* W_hh3, const float* b_ih3, const float* b_hh3,
          const float* W_dec, const float* b_dec, float* __restrict__ out) {
    extern __shared__ __align__(16) char smem_dyn[];
    unsigned long long* s_mbar = (unsigned long long*)smem_dyn;   // 9 barriers in 128 B
    char* wbuf = smem_dyn + HDR;                                  // 9 x 16 KB
    float* red = (float*)(smem_dyn + REDOFF);                     // 2 x 256 x 17 floats

    int ct = blockIdx.x, tid = threadIdx.x;
    int g = tid >> 8, w = tid >> 5, mt = w & 7, lane = tid & 31;

    // phase 0: formatting
    fmt_slice(g_W1, W_ih1, W_hh1, KS1, 8 * KSX, INF, ct, tid);
    fmt_slice(g_W2, W_ih2, W_hh2, KS2, 1024, 1024, ct, tid);
    fmt_slice(g_W3, W_ih3, W_hh3, KS2, 1024, 1024, ct, tid);
    if (ct < DCTA) {
        for (int i = tid; i < KSD * 32; i += NTHR) {
            int ln = i & 31, ks = i >> 5;
            int orow = (ct << 3) + (ln >> 2);
            int k0 = (ks << 3) + (ln & 3);
            float v0 = (orow < OUTF) ? W_dec[orow * HIDQ + k0] : 0.f;
            float v1 = (orow < OUTF) ? W_dec[orow * HIDQ + k0 + 4] : 0.f;
            g_Wd[(size_t)ct * KSD * 32 + i] = make_float2(tf32r(v0), tf32r(v1));
        }
    }
    int gidx = ct * NTHR + tid;
    const int gstr = NCTA * NTHR;
    for (int i = gidx; i < TQ * KSX * 256; i += gstr) {
        int ln = i & 31, m2 = (i >> 5) & 7, ks = (i >> 8) % KSX, t = i / (KSX * 256);
        int r = ln >> 2, cc = ln & 3;
        int b0 = (m2 << 4) + r, f0 = (ks << 3) + cc;
        ((float4*)g_xfrag)[i] = make_float4(ldx(seq, b0, t, f0), ldx(seq, b0 + 8, t, f0),
                                            ldx(seq, b0, t, f0 + 4), ldx(seq, b0 + 8, t, f0 + 4));
    }
    for (int i = gidx; i < 2 * HFR; i += gstr) { g_h1[i] = 0.f; g_h2[i] = 0.f; g_h3[i] = 0.f; }
    for (int i = gidx; i < 2 * XFR; i += gstr) g_of[i] = 0.f;
    for (int i = gidx; i < 12288 + 176; i += gstr) {
        if (i < 4096) g_bias1[i] = b_ih1[i] + b_hh1[i];
        else if (i < 8192) { int k = i - 4096; g_bias2[k] = b_ih2[k] + b_hh2[k]; }
        else if (i < 12288) { int k = i - 8192; g_bias3[k] = b_ih3[k] + b_hh3[k]; }
        else { int oc = i - 12288; g_biasd[oc] = (oc < OUTF) ? b_dec[oc] : 0.f; }
    }

    uint32_t wsm[NBUF], mb[NBUF];
#pragma unroll
    for (int i = 0; i < NBUF; ++i) {
        wsm[i] = smem_u32(wbuf + (size_t)(g * NBUF + i) * CHB);
        mb[i] = smem_u32(&s_mbar[g * NBUF + i]);
    }
    if (tid == 0) {
        for (int i = 0; i < NGRP * NBUF; ++i) mbar_init(smem_u32(&s_mbar[i]), 1);
    }
    __threadfence();
    gridbar();
    asm volatile("fence.proxy.async;" ::: "memory");

    // phase 1: recurrence
    int ph[NBUF] = {0, 0, 0};
    int cn = *pcn, gn = *pgn;
    int cyc = cn + gn;
    if (cyc <= 0) cyc = 1;
    float c1[4] = {0, 0, 0, 0}, c2[4] = {0, 0, 0, 0}, c3[4] = {0, 0, 0, 0};
    float acc[16];
    const char* w1src = (const char*)(g_W1 + (size_t)ct * KS1 * 128);
    const char* w2src = (const char*)(g_W2 + (size_t)ct * KS2 * 128);
    const char* w3src = (const char*)(g_W3 + (size_t)ct * KS2 * 128);
    const int rb = (mt * 32 + lane) * 17;   // within-zone offset for this warp-slot

    for (int t = 0; t < TQ; ++t) {
        int p = t & 1, q = p ^ 1;
        int use_gt = (t % cyc) < gn;
        const float* xsrc = use_gt ? (g_xfrag + (size_t)t * XFR) : (g_of + (size_t)q * XFR);

#pragma unroll 1
        for (int L = 0; L < 3; ++L) {
            const float* A0 = (L == 0) ? xsrc : ((L == 1) ? g_h1 + (size_t)p * HFR
                                                          : g_h2 + (size_t)p * HFR);
            const float* A1 = (L == 0) ? g_h1 + (size_t)q * HFR
                              : ((L == 1) ? g_h2 + (size_t)q * HFR : g_h3 + (size_t)q * HFR);
            int nks0 = (L == 0) ? KSX : KSH;
            const char* wsrc = (L == 0) ? w1src : ((L == 1) ? w2src : w3src);
            const float* bias = (L == 0) ? g_bias1 : ((L == 1) ? g_bias2 : g_bias3);
            float* cst = (L == 0) ? c1 : ((L == 1) ? c2 : c3);
            float* hdst = (L == 0) ? g_h1 + (size_t)p * HFR
                          : ((L == 1) ? g_h2 + (size_t)p * HFR : g_h3 + (size_t)p * HFR);
            int cb0 = (L == 0) ? c_cb1[g] : c_cb2[g];
            int cb1v = (L == 0) ? c_cb1[g + 1] : c_cb2[g + 1];

            if (g == 0) initacc(acc, bias, ct, lane);
            else {
#pragma unroll
                for (int i = 0; i < 16; ++i) acc[i] = 0.f;
            }
            layer_mm(acc, A0, A1, nks0, cb0 << 4, (cb1v - cb0) << 4, wsrc,
                     wsm, mb, ph, g, tid, mt, lane);
            __syncthreads();
            if (g > 0) {
                float* z = red + (g - 1) * 256 * 17 + rb;
#pragma unroll
                for (int i = 0; i < 16; ++i) z[i] = acc[i];
            }
            __syncthreads();
            if (g == 0) {
                const float* z0 = red + rb;
                const float* z1 = red + 256 * 17 + rb;
#pragma unroll
                for (int i = 0; i < 16; ++i) acc[i] += z0[i] + z1[i];
                lstm_epi(acc, cst, hdst, ct, mt, lane);
            }
            gridbar();
        }

        // decoder (CTAs 0..21, group 0 warps) — depth-4 ring
        if (ct < DCTA && g == 0) {
            float d0 = g_biasd[(ct << 3) + ((lane & 3) << 1)];
            float d1 = g_biasd[(ct << 3) + ((lane & 3) << 1) + 1];
            float dacc[4] = {d0, d1, d0, d1};
            const float2* wp = g_Wd + (size_t)ct * KSD * 32 + lane;
            const float4* A4 = (const float4*)(g_h3 + (size_t)p * HFR);
            float4 adb[4]; float2 wdb[4];
#pragma unroll
            for (int i = 0; i < 4; ++i) {
                adb[i] = __ldcg(A4 + (i * 8 + mt) * 32 + lane);
                wdb[i] = wp[i * 32];
            }
#pragma unroll 4
            for (int ks = 0; ks < KSD; ++ks) {
                int s = ks & 3;
                float4 a = adb[s]; float2 b = wdb[s];
                int pf = ks + 4;
                if (pf < KSD) {
                    adb[s] = __ldcg(A4 + (pf * 8 + mt) * 32 + lane);
                    wdb[s] = wp[pf * 32];
                }
                mma8(dacc, __float_as_uint(a.x), __float_as_uint(a.y), __float_as_uint(a.z),
                     __float_as_uint(a.w), __float_as_uint(b.x), __float_as_uint(b.y));
            }
            float* ofr = g_of + (size_t)p * XFR;
#pragma unroll
            for (int j = 0; j < 4; ++j) {
                int r = (lane >> 2) + ((j & 2) << 2);
                int c = ((lane & 3) << 1) + (j & 1);
                int b = (mt << 4) + r;
                int oc = (ct << 3) + c;
                if (oc < OUTF) out[(b * TQ + t) * OUTF + oc] = dacc[j];
                int aq = ((c >= 4) ? 2 : 0) + ((r >= 8) ? 1 : 0);
                int lp = ((r & 7) << 2) + (c & 3);
                ofr[((((ct << 3) + mt) << 5) + lp) * 4 + aq] = tf32r(dacc[j]);
            }
        }
        int next_nontf = (t + 1 < TQ) && (((t + 1) % cyc) >= gn);
        if (next_nontf) gridbar();
    }
}

extern "C" void kernel_launch(void* const* d_in, const int* in_sizes, int n_in,
                              void* d_out, int out_size) {
    static int smem_set = 0;
    if (!smem_set) {
        cudaFuncSetAttribute(lstm_main, cudaFuncAttributeMaxDynamicSharedMemorySize, SMEMSZ);
        smem_set = 1;
    }
    lstm_main<<<NCTA, NTHR, SMEMSZ>>>(
        (const float*)d_in[0], (const int*)d_in[1], (const int*)d_in[2],
        (const float*)d_in[3], (const float*)d_in[4], (const float*)d_in[5],
        (const float*)d_in[6], (const float*)d_in[7], (const float*)d_in[8],
        (const float*)d_in[9], (const float*)d_in[10], (const float*)d_in[11],
        (const float*)d_in[12], (const float*)d_in[13], (const float*)d_in[14],
        (const float*)d_in[15], (const float*)d_in[16], (float*)d_out);
}

// round 15
// speedup vs baseline: 1.0874x; 1.0874x over previous
#include <cuda_runtime.h>
#include <cstdint>

#define NCTA 128
#define NTHR 768
#define NGRP 3
#define TQ   200
#define INF  171
#define OUTF 171
#define HIDQ 1024
#define KSX  32
#define KSH  128
#define KS1  (KSX + KSH)   // 160 = 10 chunks
#define KS2  (2 * KSH)     // 256 = 16 chunks
#define KSD  128
#define DCTA 22
#define HFR  (KSH * 1024)
#define XFR  (KSX * 1024)
#define CHKS 16
#define CHB  (CHKS * 1024)
#define NBUF 3
#define HDR  128                                  // 9 mbarriers
#define REDOFF (HDR + NGRP * NBUF * CHB)          // after 9 ring slots
#define SMEMSZ (REDOFF + 2 * 256 * 17 * 4)        // + two 17-padded acc zones

__device__ __align__(16) float2 g_W1[NCTA * KS1 * 128];
__device__ __align__(16) float2 g_W2[NCTA * KS2 * 128];
__device__ __align__(16) float2 g_W3[NCTA * KS2 * 128];
__device__ __align__(16) float2 g_Wd[DCTA * KSD * 32];
__device__ float g_bias1[4 * HIDQ];
__device__ float g_bias2[4 * HIDQ];
__device__ float g_bias3[4 * HIDQ];
__device__ float g_biasd[176];
__device__ __align__(16) float g_xfrag[TQ * XFR];
__device__ __align__(16) float g_h1[2 * HFR];
__device__ __align__(16) float g_h2[2 * HFR];
__device__ __align__(16) float g_h3[2 * HFR];
__device__ __align__(16) float g_of[2 * XFR];
__device__ unsigned g_cnt;
__device__ volatile unsigned g_gen;

// group 0 gets the smallest share (it also runs init/reduce/epilogue)
__constant__ int c_cb1[4] = {0, 3, 6, 10};   // layer1 chunk bases: {3,3,4}
__constant__ int c_cb2[4] = {0, 5, 10, 16};  // layer2/3 chunk bases: {5,5,6}

__device__ __forceinline__ float tf32r(float x) {
    uint32_t y;
    asm("cvt.rna.tf32.f32 %0, %1;" : "=r"(y) : "f"(x));
    return __uint_as_float(y);
}
__device__ __forceinline__ void mma8(float* c, uint32_t a0, uint32_t a1, uint32_t a2,
                                     uint32_t a3, uint32_t b0, uint32_t b1) {
    asm("mma.sync.aligned.m16n8k8.row.col.f32.tf32.tf32.f32 "
        "{%0,%1,%2,%3},{%4,%5,%6,%7},{%8,%9},{%0,%1,%2,%3};"
        : "+f"(c[0]), "+f"(c[1]), "+f"(c[2]), "+f"(c[3])
        : "r"(a0), "r"(a1), "r"(a2), "r"(a3), "r"(b0), "r"(b1));
}
__device__ __forceinline__ float sigm(float x) { return 1.f / (1.f + __expf(-x)); }
__device__ __forceinline__ uint32_t smem_u32(const void* p) {
    return (uint32_t)__cvta_generic_to_shared(p);
}
__device__ __forceinline__ void mbar_init(uint32_t a, uint32_t cnt) {
    asm volatile("mbarrier.init.shared.b64 [%0], %1;" :: "r"(a), "r"(cnt) : "memory");
}
__device__ __forceinline__ void mbar_expect_tx(uint32_t a, uint32_t bytes) {
    asm volatile("mbarrier.arrive.expect_tx.shared.b64 _, [%0], %1;"
                 :: "r"(a), "r"(bytes) : "memory");
}
__device__ __forceinline__ void bulk_g2s(uint32_t dst, const void* src, uint32_t bytes,
                                         uint32_t mbar) {
    asm volatile("cp.async.bulk.shared::cta.global.mbarrier::complete_tx::bytes "
                 "[%0], [%1], %2, [%3];"
                 :: "r"(dst), "l"(src), "r"(bytes), "r"(mbar) : "memory");
}
__device__ __forceinline__ void mbar_wait(uint32_t a, int parity) {
    asm volatile(
        "{\n\t.reg .pred P;\n\t"
        "WL%=:\n\t"
        "mbarrier.try_wait.parity.acquire.cta.shared::cta.b64 P, [%0], %1, 0x989680;\n\t"
        "@!P bra WL%=;\n\t}"
        :: "r"(a), "r"(parity) : "memory");
}
__device__ __forceinline__ float4 lds128(uint32_t a) {
    float4 v;
    asm volatile("ld.shared.v4.f32 {%0,%1,%2,%3}, [%4];"
                 : "=f"(v.x), "=f"(v.y), "=f"(v.z), "=f"(v.w) : "r"(a));
    return v;
}
__device__ __forceinline__ void barg(int g) {   // per-group named barrier (256 thr)
    asm volatile("bar.sync %0, %1;" :: "r"(g + 1), "r"(256) : "memory");
}

// monotonic grid barrier; all 128 CTAs resident (1/SM)
__device__ __forceinline__ void gridbar() {
    __syncthreads();
    if (threadIdx.x == 0) {
        __threadfence();
        unsigned arr = atomicAdd(&g_cnt, 1u);
        unsigned mygen = arr / NCTA + 1u;
        if (arr % NCTA == NCTA - 1u) {
            __threadfence();
            g_gen = mygen;
        } else {
            while ((int)(g_gen - mygen) < 0) { __nanosleep(32); }
        }
        __threadfence();
    }
    __syncthreads();
}

__device__ __forceinline__ void initacc(float acc[16], const float* bias, int ct, int lane) {
#pragma unroll
    for (int nt = 0; nt < 4; ++nt) {
        int col = nt * HIDQ + (ct << 3) + ((lane & 3) << 1);
        float b0 = bias[col], b1 = bias[col + 1];
        acc[4 * nt] = b0; acc[4 * nt + 1] = b1;
        acc[4 * nt + 2] = b0; acc[4 * nt + 3] = b1;
    }
}

// group-local GEMM span over ks [ksbase, ksbase+nksg): A via depth-4 __ldcg ring,
// W via this group's 3-deep TMA ring. nksg multiple of 16.
__device__ __forceinline__ void layer_mm(float acc[16], const float* A0, const float* A1,
                                         int nks0, int ksbase, int nksg, const char* wsrc,
                                         const uint32_t* wsm, const uint32_t* mb, int* ph,
                                         int g, int tid, int mt, int lane) {
    const float4* A04 = (const float4*)A0;
    const float4* A14 = (const float4*)A1;
    float4 ab[4];
#pragma unroll
    for (int i = 0; i < 4; ++i) {
        int ks = ksbase + i;
        const float4* src = (ks < nks0) ? (A04 + (ks * 8 + mt) * 32)
                                        : (A14 + ((ks - nks0) * 8 + mt) * 32);
        ab[i] = __ldcg(src + lane);
    }
    int nch = nksg >> 4;
    const char* wg = wsrc + (size_t)(ksbase >> 4) * CHB;
    if ((tid & 255) == 0) {
#pragma unroll
        for (int k = 0; k < 2; ++k) {
            mbar_expect_tx(mb[k], CHB);
            bulk_g2s(wsm[k], wg + (size_t)k * CHB, CHB, mb[k]);
        }
    }
    for (int c = 0; c < nch; ++c) {
        int b = c % NBUF;
        mbar_wait(mb[b], ph[b]);
        ph[b] ^= 1;
        uint32_t wb = wsm[b] + (lane << 4);
#pragma unroll
        for (int j = 0; j < 16; ++j) {
            int ksl = (c << 4) + j;
            int s = ksl & 3;
            float4 a = ab[s];
            int pf = ksl + 4;
            if (pf < nksg) {
                int ks = ksbase + pf;
                const float4* src = (ks < nks0) ? (A04 + (ks * 8 + mt) * 32)
                                                : (A14 + ((ks - nks0) * 8 + mt) * 32);
                ab[s] = __ldcg(src + lane);
            }
            float4 w0 = lds128(wb + j * 1024);
            float4 w1 = lds128(wb + j * 1024 + 512);
            uint32_t a0 = __float_as_uint(a.x), a1 = __float_as_uint(a.y);
            uint32_t a2 = __float_as_uint(a.z), a3 = __float_as_uint(a.w);
            mma8(acc + 0,  a0, a1, a2, a3, __float_as_uint(w0.x), __float_as_uint(w0.y));
            mma8(acc + 4,  a0, a1, a2, a3, __float_as_uint(w0.z), __float_as_uint(w0.w));
            mma8(acc + 8,  a0, a1, a2, a3, __float_as_uint(w1.x), __float_as_uint(w1.y));
            mma8(acc + 12, a0, a1, a2, a3, __float_as_uint(w1.z), __float_as_uint(w1.w));
        }
        barg(g);
        if ((tid & 255) == 0 && c + 2 < nch) {
            int b2 = (c + 2) % NBUF;
            mbar_expect_tx(mb[b2], CHB);
            bulk_g2s(wsm[b2], wg + (size_t)(c + 2) * CHB, CHB, mb[b2]);
        }
    }
}

__device__ __forceinline__ void lstm_epi(const float acc[16], float cst[4], float* hdst,
                                         int ct, int mt, int lane) {
#pragma unroll
    for (int j = 0; j < 4; ++j) {
        float ig = sigm(acc[0 + j]);
        float fg = sigm(acc[4 + j]);
        float gg = tanhf(acc[8 + j]);
        float og = sigm(acc[12 + j]);
        float cc = fg * cst[j] + ig * gg;
        cst[j] = cc;
        float h = og * tanhf(cc);
        int r = (lane >> 2) + ((j & 2) << 2);
        int c = ((lane & 3) << 1) + (j & 1);
        int aq = ((c >= 4) ? 2 : 0) + ((r >= 8) ? 1 : 0);
        int lp = ((r & 7) << 2) + (c & 3);
        hdst[((((ct << 3) + mt) << 5) + lp) * 4 + aq] = tf32r(h);
    }
}

__device__ __forceinline__ float wfetch(const float* Wih, const float* Whh, int gr, int k,
                                        int kxt, int kxv) {
    if (k < kxt) return (k < kxv) ? Wih[gr * kxv + k] : 0.f;
    return Whh[gr * HIDQ + (k - kxt)];
}
__device__ __forceinline__ void fmt_slice(float2* dst, const float* Wih, const float* Whh,
                                          int KS, int kxt, int kxv, int ct, int tid) {
    for (int i = tid; i < KS * 128; i += NTHR) {
        int nt = i & 3;
        int lane = (i >> 2) & 31;
        int ks = i >> 7;
        int gr = nt * HIDQ + (ct << 3) + (lane >> 2);
        int k0 = (ks << 3) + (lane & 3);
        float v0 = wfetch(Wih, Whh, gr, k0, kxt, kxv);
        float v1 = wfetch(Wih, Whh, gr, k0 + 4, kxt, kxv);
        size_t off = ((size_t)ct * KS + ks) * 128 + (nt >> 1) * 64 + lane * 2 + (nt & 1);
        dst[off] = make_float2(tf32r(v0), tf32r(v1));
    }
}
__device__ __forceinline__ float ldx(const float* s, int b, int t, int f) {
    return (f < INF) ? tf32r(s[(b * TQ + t) * INF + f]) : 0.f;
}

// ---------------- single fused kernel: setup + persistent LSTM ----------------
__global__ void __launch_bounds__(NTHR, 1)
lstm_main(const float* __restrict__ seq, const int* __restrict__ pcn,
          const int* __restrict__ pgn,
          const float* W_ih1, const float* W_hh1, const float* b_ih1, const float* b_hh1,
          const float* W_ih2, const float* W_hh2, const float* b_ih2, const float* b_hh2,
          const float* W_ih3, const float* W_hh3, const float* b_ih3, const float* b_hh3,
          const float* W_dec, const float* b_dec, float* __restrict__ out) {
    extern __shared__ __align__(16) char smem_dyn[];
    unsigned long long* s_mbar = (unsigned long long*)smem_dyn;   // 9 barriers in 128 B
    char* wbuf = smem_dyn + HDR;                                  // 9 x 16 KB
    float* red = (float*)(smem_dyn + REDOFF);                     // 2 x 256 x 17 floats

    int ct = blockIdx.x, tid = threadIdx.x;
    int g = tid >> 8, w = tid >> 5, mt = w & 7, lane = tid & 31;

    // phase 0: formatting
    fmt_slice(g_W1, W_ih1, W_hh1, KS1, 8 * KSX, INF, ct, tid);
    fmt_slice(g_W2, W_ih2, W_hh2, KS2, 1024, 1024, ct, tid);
    fmt_slice(g_W3, W_ih3, W_hh3, KS2, 1024, 1024, ct, tid);
    if (ct < DCTA) {
        for (int i = tid; i < KSD * 32; i += NTHR) {
            int ln = i & 31, ks = i >> 5;
            int orow = (ct << 3) + (ln >> 2);
            int k0 = (ks << 3) + (ln & 3);
            float v0 = (orow < OUTF) ? W_dec[orow * HIDQ + k0] : 0.f;
            float v1 = (orow < OUTF) ? W_dec[orow * HIDQ + k0 + 4] : 0.f;
            g_Wd[(size_t)ct * KSD * 32 + i] = make_float2(tf32r(v0), tf32r(v1));
        }
    }
    int gidx = ct * NTHR + tid;
    const int gstr = NCTA * NTHR;
    for (int i = gidx; i < TQ * KSX * 256; i += gstr) {
        int ln = i & 31, m2 = (i >> 5) & 7, ks = (i >> 8) % KSX, t = i / (KSX * 256);
        int r = ln >> 2, cc = ln & 3;
        int b0 = (m2 << 4) + r, f0 = (ks << 3) + cc;
        ((float4*)g_xfrag)[i] = make_float4(ldx(seq, b0, t, f0), ldx(seq, b0 + 8, t, f0),
                                            ldx(seq, b0, t, f0 + 4), ldx(seq, b0 + 8, t, f0 + 4));
    }
    for (int i = gidx; i < 2 * HFR; i += gstr) { g_h1[i] = 0.f; g_h2[i] = 0.f; g_h3[i] = 0.f; }
    for (int i = gidx; i < 2 * XFR; i += gstr) g_of[i] = 0.f;
    for (int i = gidx; i < 12288 + 176; i += gstr) {
        if (i < 4096) g_bias1[i] = b_ih1[i] + b_hh1[i];
        else if (i < 8192) { int k = i - 4096; g_bias2[k] = b_ih2[k] + b_hh2[k]; }
        else if (i < 12288) { int k = i - 8192; g_bias3[k] = b_ih3[k] + b_hh3[k]; }
        else { int oc = i - 12288; g_biasd[oc] = (oc < OUTF) ? b_dec[oc] : 0.f; }
    }

    uint32_t wsm[NBUF], mb[NBUF];
#pragma unroll
    for (int i = 0; i < NBUF; ++i) {
        wsm[i] = smem_u32(wbuf + (size_t)(g * NBUF + i) * CHB);
        mb[i] = smem_u32(&s_mbar[g * NBUF + i]);
    }
    if (tid == 0) {
        for (int i = 0; i < NGRP * NBUF; ++i) mbar_init(smem_u32(&s_mbar[i]), 1);
    }
    __threadfence();
    gridbar();
    asm volatile("fence.proxy.async;" ::: "memory");

    // phase 1: recurrence
    int ph[NBUF] = {0, 0, 0};
    int cn = *pcn, gn = *pgn;
    int cyc = cn + gn;
    if (cyc <= 0) cyc = 1;
    float c1[4] = {0, 0, 0, 0}, c2[4] = {0, 0, 0, 0}, c3[4] = {0, 0, 0, 0};
    float acc[16];
    const char* w1src = (const char*)(g_W1 + (size_t)ct * KS1 * 128);
    const char* w2src = (const char*)(g_W2 + (size_t)ct * KS2 * 128);
    const char* w3src = (const char*)(g_W3 + (size_t)ct * KS2 * 128);
    const int rb = (mt * 32 + lane) * 17;   // within-zone offset for this warp-slot

    for (int t = 0; t < TQ; ++t) {
        int p = t & 1, q = p ^ 1;
        int use_gt = (t % cyc) < gn;
        const float* xsrc = use_gt ? (g_xfrag + (size_t)t * XFR) : (g_of + (size_t)q * XFR);

#pragma unroll 1
        for (int L = 0; L < 3; ++L) {
            const float* A0 = (L == 0) ? xsrc : ((L == 1) ? g_h1 + (size_t)p * HFR
                                                          : g_h2 + (size_t)p * HFR);
            const float* A1 = (L == 0) ? g_h1 + (size_t)q * HFR
                              : ((L == 1) ? g_h2 + (size_t)q * HFR : g_h3 + (size_t)q * HFR);
            int nks0 = (L == 0) ? KSX : KSH;
            const char* wsrc = (L == 0) ? w1src : ((L == 1) ? w2src : w3src);
            const float* bias = (L == 0) ? g_bias1 : ((L == 1) ? g_bias2 : g_bias3);
            float* cst = (L == 0) ? c1 : ((L == 1) ? c2 : c3);
            float* hdst = (L == 0) ? g_h1 + (size_t)p * HFR
                          : ((L == 1) ? g_h2 + (size_t)p * HFR : g_h3 + (size_t)p * HFR);
            int cb0 = (L == 0) ? c_cb1[g] : c_cb2[g];
            int cb1v = (L == 0) ? c_cb1[g + 1] : c_cb2[g + 1];

            if (g == 0) initacc(acc, bias, ct, lane);
            else {
#pragma unroll
                for (int i = 0; i < 16; ++i) acc[i] = 0.f;
            }
            layer_mm(acc, A0, A1, nks0, cb0 << 4, (cb1v - cb0) << 4, wsrc,
                     wsm, mb, ph, g, tid, mt, lane);
            __syncthreads();
            if (g > 0) {
                float* z = red + (g - 1) * 256 * 17 + rb;
#pragma unroll
                for (int i = 0; i < 16; ++i) z[i] = acc[i];
            }
            __syncthreads();
            if (g == 0) {
                const float* z0 = red + rb;
                const float* z1 = red + 256 * 17 + rb;
#pragma unroll
                for (int i = 0; i < 16; ++i) acc[i] += z0[i] + z1[i];
                lstm_epi(acc, cst, hdst, ct, mt, lane);
            }
            gridbar();
        }

        // decoder (CTAs 0..21, group 0 warps) — depth-4 ring
        if (ct < DCTA && g == 0) {
            float d0 = g_biasd[(ct << 3) + ((lane & 3) << 1)];
            float d1 = g_biasd[(ct << 3) + ((lane & 3) << 1) + 1];
            float dacc[4] = {d0, d1, d0, d1};
            const float2* wp = g_Wd + (size_t)ct * KSD * 32 + lane;
            const float4* A4 = (const float4*)(g_h3 + (size_t)p * HFR);
            float4 adb[4]; float2 wdb[4];
#pragma unroll
            for (int i = 0; i < 4; ++i) {
                adb[i] = __ldcg(A4 + (i * 8 + mt) * 32 + lane);
                wdb[i] = wp[i * 32];
            }
#pragma unroll 4
            for (int ks = 0; ks < KSD; ++ks) {
                int s = ks & 3;
                float4 a = adb[s]; float2 b = wdb[s];
                int pf = ks + 4;
                if (pf < KSD) {
                    adb[s] = __ldcg(A4 + (pf * 8 + mt) * 32 + lane);
                    wdb[s] = wp[pf * 32];
                }
                mma8(dacc, __float_as_uint(a.x), __float_as_uint(a.y), __float_as_uint(a.z),
                     __float_as_uint(a.w), __float_as_uint(b.x), __float_as_uint(b.y));
            }
            float* ofr = g_of + (size_t)p * XFR;
#pragma unroll
            for (int j = 0; j < 4; ++j) {
                int r = (lane >> 2) + ((j & 2) << 2);
                int c = ((lane & 3) << 1) + (j & 1);
                int b = (mt << 4) + r;
                int oc = (ct << 3) + c;
                if (oc < OUTF) out[(b * TQ + t) * OUTF + oc] = dacc[j];
                int aq = ((c >= 4) ? 2 : 0) + ((r >= 8) ? 1 : 0);
                int lp = ((r & 7) << 2) + (c & 3);
                ofr[((((ct << 3) + mt) << 5) + lp) * 4 + aq] = tf32r(dacc[j]);
            }
        }
        int next_nontf = (t + 1 < TQ) && (((t + 1) % cyc) >= gn);
        if (next_nontf) gridbar();
    }
}

extern "C" void kernel_launch(void* const* d_in, const int* in_sizes, int n_in,
                              void* d_out, int out_size) {
    static int smem_set = 0;
    if (!smem_set) {
        cudaFuncSetAttribute(lstm_main, cudaFuncAttributeMaxDynamicSharedMemorySize, SMEMSZ);
        smem_set = 1;
    }
    lstm_main<<<NCTA, NTHR, SMEMSZ>>>(
        (const float*)d_in[0], (const int*)d_in[1], (const int*)d_in[2],
        (const float*)d_in[3], (const float*)d_in[4], (const float*)d_in[5],
        (const float*)d_in[6], (const float*)d_in[7], (const float*)d_in[8],
        (const float*)d_in[9], (const float*)d_in[10], (const float*)d_in[11],
        (const float*)d_in[12], (const float*)d_in[13], (const float*)d_in[14],
        (const float*)d_in[15], (const float*)d_in[16], (float*)d_out);
}

// round 17
// speedup vs baseline: 1.1716x; 1.0774x over previous
#include <cuda_runtime.h>
#include <cstdint>

#define NCTA 128
#define NTHR 512
#define TQ   200
#define INF  171
#define OUTF 171
#define HIDQ 1024
#define KSX  32
#define KSH  128
#define KS1  (KSX + KSH)   // 160 = 10 chunks
#define KS2  (2 * KSH)     // 256 = 16 chunks
#define KSD  128
#define DCTA 22
#define HFR  (KSH * 1024)
#define XFR  (KSX * 1024)
#define CHB  16384
#define NSEQ 21            // per-group chunks per step: 5 + 8 + 8
#define HDR  64
#define REDOFF (HDR + 6 * CHB)
#define SMEMSZ (REDOFF + 256 * 17 * 4)

__device__ __align__(16) float2 g_W1[NCTA * KS1 * 128];
__device__ __align__(16) float2 g_W2[NCTA * KS2 * 128];
__device__ __align__(16) float2 g_W3[NCTA * KS2 * 128];
__device__ __align__(16) float2 g_Wd[DCTA * KSD * 32];
__device__ float g_bias1[4 * HIDQ];
__device__ float g_bias2[4 * HIDQ];
__device__ float g_bias3[4 * HIDQ];
__device__ float g_biasd[176];
__device__ __align__(16) float g_xfrag[TQ * XFR];
__device__ __align__(16) float g_h1[2 * HFR];
__device__ __align__(16) float g_h2[2 * HFR];
__device__ __align__(16) float g_h3[2 * HFR];
__device__ __align__(16) float g_of[2 * XFR];
__device__ volatile unsigned g_flags[NCTA * 32];   // 128B-padded arrival flags
__device__ volatile unsigned g_gen;

__device__ __forceinline__ float tf32r(float x) {
    uint32_t y;
    asm("cvt.rna.tf32.f32 %0, %1;" : "=r"(y) : "f"(x));
    return __uint_as_float(y);
}
__device__ __forceinline__ void mma8(float* c, uint32_t a0, uint32_t a1, uint32_t a2,
                                     uint32_t a3, uint32_t b0, uint32_t b1) {
    asm("mma.sync.aligned.m16n8k8.row.col.f32.tf32.tf32.f32 "
        "{%0,%1,%2,%3},{%4,%5,%6,%7},{%8,%9},{%0,%1,%2,%3};"
        : "+f"(c[0]), "+f"(c[1]), "+f"(c[2]), "+f"(c[3])
        : "r"(a0), "r"(a1), "r"(a2), "r"(a3), "r"(b0), "r"(b1));
}
__device__ __forceinline__ float sigm(float x) { return 1.f / (1.f + __expf(-x)); }
__device__ __forceinline__ uint32_t smem_u32(const void* p) {
    return (uint32_t)__cvta_generic_to_shared(p);
}
__device__ __forceinline__ void mbar_init(uint32_t a, uint32_t cnt) {
    asm volatile("mbarrier.init.shared.b64 [%0], %1;" :: "r"(a), "r"(cnt) : "memory");
}
__device__ __forceinline__ void mbar_expect_tx(uint32_t a, uint32_t bytes) {
    asm volatile("mbarrier.arrive.expect_tx.shared.b64 _, [%0], %1;"
                 :: "r"(a), "r"(bytes) : "memory");
}
__device__ __forceinline__ void bulk_g2s(uint32_t dst, const void* src, uint32_t bytes,
                                         uint32_t mbar) {
    asm volatile("cp.async.bulk.shared::cta.global.mbarrier::complete_tx::bytes "
                 "[%0], [%1], %2, [%3];"
                 :: "r"(dst), "l"(src), "r"(bytes), "r"(mbar) : "memory");
}
__device__ __forceinline__ void mbar_wait(uint32_t a, int parity) {
    asm volatile(
        "{\n\t.reg .pred P;\n\t"
        "WL%=:\n\t"
        "mbarrier.try_wait.parity.acquire.cta.shared::cta.b64 P, [%0], %1, 0x989680;\n\t"
        "@!P bra WL%=;\n\t}"
        :: "r"(a), "r"(parity) : "memory");
}
__device__ __forceinline__ float4 lds128(uint32_t a) {
    float4 v;
    asm volatile("ld.shared.v4.f32 {%0,%1,%2,%3}, [%4];"
                 : "=f"(v.x), "=f"(v.y), "=f"(v.z), "=f"(v.w) : "r"(a));
    return v;
}
__device__ __forceinline__ void barg(int g) {   // per-group named barrier (256 thr)
    asm volatile("bar.sync %0, %1;" :: "r"(g + 1), "r"(256) : "memory");
}

// contention-free flag barrier: CTA writes its own flag; CTA0 warp0 aggregates.
__device__ __forceinline__ void gridbar(int ct, unsigned gen) {
    __syncthreads();
    if (threadIdx.x < 32) {
        if (threadIdx.x == 0) { __threadfence(); g_flags[ct * 32] = gen; }
        if (ct == 0) {
            for (;;) {
                int l = threadIdx.x;
                unsigned v0 = g_flags[l * 32], v1 = g_flags[(l + 32) * 32];
                unsigned v2 = g_flags[(l + 64) * 32], v3 = g_flags[(l + 96) * 32];
                bool ok = ((int)(v0 - gen) >= 0) && ((int)(v1 - gen) >= 0) &&
                          ((int)(v2 - gen) >= 0) && ((int)(v3 - gen) >= 0);
                if (__all_sync(0xffffffffu, ok)) break;
                __nanosleep(64);
            }
            if (threadIdx.x == 0) { __threadfence(); g_gen = gen; }
        } else if (threadIdx.x == 0) {
            while ((int)(g_gen - gen) < 0) { __nanosleep(32); }
            __threadfence();
        }
    }
    __syncthreads();
}

__device__ __forceinline__ void initacc(float acc[16], const float* bias, int ct, int lane) {
#pragma unroll
    for (int nt = 0; nt < 4; ++nt) {
        int col = nt * HIDQ + (ct << 3) + ((lane & 3) << 1);
        float b0 = bias[col], b1 = bias[col + 1];
        acc[4 * nt] = b0; acc[4 * nt + 1] = b1;
        acc[4 * nt + 2] = b0; acc[4 * nt + 3] = b1;
    }
}

// address of chunk cs (0..20) in this group's per-step weight stream
__device__ __forceinline__ const char* wsrc_of(int g, int cs, const char* w1,
                                               const char* w2, const char* w3) {
    if (cs < 5)  return w1 + (size_t)(g * 5 + cs) * CHB;
    if (cs < 13) return w2 + (size_t)(g * 8 + (cs - 5)) * CHB;
    return w3 + (size_t)(g * 8 + (cs - 13)) * CHB;
}

// GEMM span: A via depth-8 __ldcg ring; W via continuous 3-deep TMA stream.
__device__ __forceinline__ void layer_mm(float acc[16], const float* A0, const float* A1,
                                         int nks0, int ksbase, int nksg, int cs0,
                                         const char* w1, const char* w2, const char* w3,
                                         const uint32_t* wsm, const uint32_t* mb, int* ph,
                                         int g, int tid, int mt, int lane, int last) {
    const float4* A04 = (const float4*)A0;
    const float4* A14 = (const float4*)A1;
    float4 ab[8];
#pragma unroll
    for (int i = 0; i < 8; ++i) {
        int ks = ksbase + i;
        const float4* src = (ks < nks0) ? (A04 + (ks * 8 + mt) * 32)
                                        : (A14 + ((ks - nks0) * 8 + mt) * 32);
        ab[i] = __ldcg(src + lane);
    }
    int nch = nksg >> 4;
    for (int cc = 0; cc < nch; ++cc) {
        int cs = cs0 + cc;
        int b = cs % 3;
        mbar_wait(mb[b], ph[b]);
        ph[b] ^= 1;
        uint32_t wb = wsm[b] + (lane << 4);
#pragma unroll
        for (int j = 0; j < 16; ++j) {
            int ksl = (cc << 4) + j;
            int s = ksl & 7;
            float4 a = ab[s];
            int pf = ksl + 8;
            if (pf < nksg) {
                int ks = ksbase + pf;
                const float4* src = (ks < nks0) ? (A04 + (ks * 8 + mt) * 32)
                                                : (A14 + ((ks - nks0) * 8 + mt) * 32);
                ab[s] = __ldcg(src + lane);
            }
            float4 w0 = lds128(wb + j * 1024);
            float4 wv = lds128(wb + j * 1024 + 512);
            uint32_t a0 = __float_as_uint(a.x), a1 = __float_as_uint(a.y);
            uint32_t a2 = __float_as_uint(a.z), a3 = __float_as_uint(a.w);
            mma8(acc + 0,  a0, a1, a2, a3, __float_as_uint(w0.x), __float_as_uint(w0.y));
            mma8(acc + 4,  a0, a1, a2, a3, __float_as_uint(w0.z), __float_as_uint(w0.w));
            mma8(acc + 8,  a0, a1, a2, a3, __float_as_uint(wv.x), __float_as_uint(wv.y));
            mma8(acc + 12, a0, a1, a2, a3, __float_as_uint(wv.z), __float_as_uint(wv.w));
        }
        barg(g);
        if ((tid & 255) == 0) {
            int f = cs + 2;
            int wrap = (f >= NSEQ);
            if (!wrap || !last) {
                if (wrap) f -= NSEQ;
                int fb = f % 3;
                mbar_expect_tx(mb[fb], CHB);
                bulk_g2s(wsm[fb], wsrc_of(g, f, w1, w2, w3), CHB, mb[fb]);
            }
        }
    }
}

__device__ __forceinline__ void lstm_epi(const float acc[16], float cst[4], float* hdst,
                                         int ct, int mt, int lane) {
#pragma unroll
    for (int j = 0; j < 4; ++j) {
        float ig = sigm(acc[0 + j]);
        float fg = sigm(acc[4 + j]);
        float gg = tanhf(acc[8 + j]);
        float og = sigm(acc[12 + j]);
        float cc = fg * cst[j] + ig * gg;
        cst[j] = cc;
        float h = og * tanhf(cc);
        int r = (lane >> 2) + ((j & 2) << 2);
        int c = ((lane & 3) << 1) + (j & 1);
        int aq = ((c >= 4) ? 2 : 0) + ((r >= 8) ? 1 : 0);
        int lp = ((r & 7) << 2) + (c & 3);
        hdst[((((ct << 3) + mt) << 5) + lp) * 4 + aq] = tf32r(h);
    }
}

__device__ __forceinline__ float wfetch(const float* Wih, const float* Whh, int gr, int k,
                                        int kxt, int kxv) {
    if (k < kxt) return (k < kxv) ? Wih[gr * kxv + k] : 0.f;
    return Whh[gr * HIDQ + (k - kxt)];
}
__device__ __forceinline__ void fmt_slice(float2* dst, const float* Wih, const float* Whh,
                                          int KS, int kxt, int kxv, int ct, int tid) {
    for (int i = tid; i < KS * 128; i += NTHR) {
        int nt = i & 3;
        int lane = (i >> 2) & 31;
        int ks = i >> 7;
        int gr = nt * HIDQ + (ct << 3) + (lane >> 2);
        int k0 = (ks << 3) + (lane & 3);
        float v0 = wfetch(Wih, Whh, gr, k0, kxt, kxv);
        float v1 = wfetch(Wih, Whh, gr, k0 + 4, kxt, kxv);
        size_t off = ((size_t)ct * KS + ks) * 128 + (nt >> 1) * 64 + lane * 2 + (nt & 1);
        dst[off] = make_float2(tf32r(v0), tf32r(v1));
    }
}
__device__ __forceinline__ float ldx(const float* s, int b, int t, int f) {
    return (f < INF) ? tf32r(s[(b * TQ + t) * INF + f]) : 0.f;
}

// ---------------- single fused kernel: setup + persistent LSTM ----------------
__global__ void __launch_bounds__(NTHR, 1)
lstm_main(const float* __restrict__ seq, const int* __restrict__ pcn,
          const int* __restrict__ pgn,
          const float* W_ih1, const float* W_hh1, const float* b_ih1, const float* b_hh1,
          const float* W_ih2, const float* W_hh2, const float* b_ih2, const float* b_hh2,
          const float* W_ih3, const float* W_hh3, const float* b_ih3, const float* b_hh3,
          const float* W_dec, const float* b_dec, float* __restrict__ out) {
    extern __shared__ __align__(16) char smem_dyn[];
    unsigned long long* s_mbar = (unsigned long long*)smem_dyn;   // 6 barriers
    char* wbuf = smem_dyn + HDR;                                  // 6 x 16 KB
    float* red = (float*)(smem_dyn + REDOFF);                     // 256 x 17 floats

    int ct = blockIdx.x, tid = threadIdx.x;
    int g = tid >> 8, w = tid >> 5, mt = w & 7, lane = tid & 31;
    unsigned gen = g_gen;   // per-launch base (stable until first release)

    // phase 0: formatting
    fmt_slice(g_W1, W_ih1, W_hh1, KS1, 8 * KSX, INF, ct, tid);
    fmt_slice(g_W2, W_ih2, W_hh2, KS2, 1024, 1024, ct, tid);
    fmt_slice(g_W3, W_ih3, W_hh3, KS2, 1024, 1024, ct, tid);
    if (ct < DCTA) {
        for (int i = tid; i < KSD * 32; i += NTHR) {
            int ln = i & 31, ks = i >> 5;
            int orow = (ct << 3) + (ln >> 2);
            int k0 = (ks << 3) + (ln & 3);
            float v0 = (orow < OUTF) ? W_dec[orow * HIDQ + k0] : 0.f;
            float v1 = (orow < OUTF) ? W_dec[orow * HIDQ + k0 + 4] : 0.f;
            g_Wd[(size_t)ct * KSD * 32 + i] = make_float2(tf32r(v0), tf32r(v1));
        }
    }
    int gidx = ct * NTHR + tid;
    const int gstr = NCTA * NTHR;
    for (int i = gidx; i < TQ * KSX * 256; i += gstr) {
        int ln = i & 31, m2 = (i >> 5) & 7, ks = (i >> 8) % KSX, t = i / (KSX * 256);
        int r = ln >> 2, cc = ln & 3;
        int b0 = (m2 << 4) + r, f0 = (ks << 3) + cc;
        ((float4*)g_xfrag)[i] = make_float4(ldx(seq, b0, t, f0), ldx(seq, b0 + 8, t, f0),
                                            ldx(seq, b0, t, f0 + 4), ldx(seq, b0 + 8, t, f0 + 4));
    }
    for (int i = gidx; i < 2 * HFR; i += gstr) { g_h1[i] = 0.f; g_h2[i] = 0.f; g_h3[i] = 0.f; }
    for (int i = gidx; i < 2 * XFR; i += gstr) g_of[i] = 0.f;
    for (int i = gidx; i < 12288 + 176; i += gstr) {
        if (i < 4096) g_bias1[i] = b_ih1[i] + b_hh1[i];
        else if (i < 8192) { int k = i - 4096; g_bias2[k] = b_ih2[k] + b_hh2[k]; }
        else if (i < 12288) { int k = i - 8192; g_bias3[k] = b_ih3[k] + b_hh3[k]; }
        else { int oc = i - 12288; g_biasd[oc] = (oc < OUTF) ? b_dec[oc] : 0.f; }
    }

    uint32_t wsm[3], mb[3];
#pragma unroll
    for (int i = 0; i < 3; ++i) {
        wsm[i] = smem_u32(wbuf + (size_t)(g * 3 + i) * CHB);
        mb[i] = smem_u32(&s_mbar[g * 3 + i]);
    }
    if (tid == 0) {
        for (int i = 0; i < 6; ++i) mbar_init(smem_u32(&s_mbar[i]), 1);
    }
    __threadfence();
    gen++; gridbar(ct, gen);
    asm volatile("fence.proxy.async;" ::: "memory");

    // phase 1: recurrence
    int ph[3] = {0, 0, 0};
    int cn = *pcn, gn = *pgn;
    int cyc = cn + gn;
    if (cyc <= 0) cyc = 1;
    float c1[4] = {0, 0, 0, 0}, c2[4] = {0, 0, 0, 0}, c3[4] = {0, 0, 0, 0};
    float acc[16];
    const char* w1src = (const char*)(g_W1 + (size_t)ct * KS1 * 128);
    const char* w2src = (const char*)(g_W2 + (size_t)ct * KS2 * 128);
    const char* w3src = (const char*)(g_W3 + (size_t)ct * KS2 * 128);
    const int rb = (mt * 32 + lane) * 17;

    // prime the continuous weight stream (chunks 0 and 1)
    if ((tid & 255) == 0) {
#pragma unroll
        for (int k = 0; k < 2; ++k) {
            mbar_expect_tx(mb[k], CHB);
            bulk_g2s(wsm[k], wsrc_of(g, k, w1src, w2src, w3src), CHB, mb[k]);
        }
    }

    for (int t = 0; t < TQ; ++t) {
        int p = t & 1, q = p ^ 1;
        int use_gt = (t % cyc) < gn;
        int last = (t == TQ - 1);
        const float* xsrc = use_gt ? (g_xfrag + (size_t)t * XFR) : (g_of + (size_t)q * XFR);

#pragma unroll 1
        for (int L = 0; L < 3; ++L) {
            const float* A0 = (L == 0) ? xsrc : ((L == 1) ? g_h1 + (size_t)p * HFR
                                                          : g_h2 + (size_t)p * HFR);
            const float* A1 = (L == 0) ? g_h1 + (size_t)q * HFR
                              : ((L == 1) ? g_h2 + (size_t)q * HFR : g_h3 + (size_t)q * HFR);
            int nks0 = (L == 0) ? KSX : KSH;
            int KS = (L == 0) ? KS1 : KS2;
            int cs0 = (L == 0) ? 0 : ((L == 1) ? 5 : 13);
            const float* bias = (L == 0) ? g_bias1 : ((L == 1) ? g_bias2 : g_bias3);
            float* cst = (L == 0) ? c1 : ((L == 1) ? c2 : c3);
            float* hdst = (L == 0) ? g_h1 + (size_t)p * HFR
                          : ((L == 1) ? g_h2 + (size_t)p * HFR : g_h3 + (size_t)p * HFR);

            if (g == 0) initacc(acc, bias, ct, lane);
            else {
#pragma unroll
                for (int i = 0; i < 16; ++i) acc[i] = 0.f;
            }
            int half = KS >> 1;
            layer_mm(acc, A0, A1, nks0, g * half, half, cs0, w1src, w2src, w3src,
                     wsm, mb, ph, g, tid, mt, lane, last);
            __syncthreads();
            if (g == 1) {
#pragma unroll
                for (int i = 0; i < 16; ++i) red[rb + i] = acc[i];
            }
            __syncthreads();
            if (g == 0) {
#pragma unroll
                for (int i = 0; i < 16; ++i) acc[i] += red[rb + i];
                lstm_epi(acc, cst, hdst, ct, mt, lane);
            }
            gen++; gridbar(ct, gen);
        }

        // decoder (CTAs 0..21, group 0 warps)
        if (ct < DCTA && g == 0) {
            float d0 = g_biasd[(ct << 3) + ((lane & 3) << 1)];
            float d1 = g_biasd[(ct << 3) + ((lane & 3) << 1) + 1];
            float dacc[4] = {d0, d1, d0, d1};
            const float2* wp = g_Wd + (size_t)ct * KSD * 32 + lane;
            const float4* A4 = (const float4*)(g_h3 + (size_t)p * HFR);
            float4 adb[8]; float2 wdb[8];
#pragma unroll
            for (int i = 0; i < 8; ++i) {
                adb[i] = __ldcg(A4 + (i * 8 + mt) * 32 + lane);
                wdb[i] = wp[i * 32];
            }
#pragma unroll 8
            for (int ks = 0; ks < KSD; ++ks) {
                int s = ks & 7;
                float4 a = adb[s]; float2 b = wdb[s];
                int pf = ks + 8;
                if (pf < KSD) {
                    adb[s] = __ldcg(A4 + (pf * 8 + mt) * 32 + lane);
                    wdb[s] = wp[pf * 32];
                }
                mma8(dacc, __float_as_uint(a.x), __float_as_uint(a.y), __float_as_uint(a.z),
                     __float_as_uint(a.w), __float_as_uint(b.x), __float_as_uint(b.y));
            }
            float* ofr = g_of + (size_t)p * XFR;
#pragma unroll
            for (int j = 0; j < 4; ++j) {
                int r = (lane >> 2) + ((j & 2) << 2);
                int c = ((lane & 3) << 1) + (j & 1);
                int b = (mt << 4) + r;
                int oc = (ct << 3) + c;
                if (oc < OUTF) out[(b * TQ + t) * OUTF + oc] = dacc[j];
                int aq = ((c >= 4) ? 2 : 0) + ((r >= 8) ? 1 : 0);
                int lp = ((r & 7) << 2) + (c & 3);
                ofr[((((ct << 3) + mt) << 5) + lp) * 4 + aq] = tf32r(dacc[j]);
            }
        }
        int next_nontf = (t + 1 < TQ) && (((t + 1) % cyc) >= gn);
        if (next_nontf) { gen++; gridbar(ct, gen); }
    }
}

extern "C" void kernel_launch(void* const* d_in, const int* in_sizes, int n_in,
                              void* d_out, int out_size) {
    static int smem_set = 0;
    if (!smem_set) {
        cudaFuncSetAttribute(lstm_main, cudaFuncAttributeMaxDynamicSharedMemorySize, SMEMSZ);
        smem_set = 1;
    }
    lstm_main<<<NCTA, NTHR, SMEMSZ>>>(
        (const float*)d_in[0], (const int*)d_in[1], (const int*)d_in[2],
        (const float*)d_in[3], (const float*)d_in[4], (const float*)d_in[5],
        (const float*)d_in[6], (const float*)d_in[7], (const float*)d_in[8],
        (const float*)d_in[9], (const float*)d_in[10], (const float*)d_in[11],
        (const float*)d_in[12], (const float*)d_in[13], (const float*)d_in[14],
        (const float*)d_in[15], (const float*)d_in[16], (float*)d_out);
}